// round 6
// baseline (speedup 1.0000x reference)
#include <cuda_runtime.h>
#include <cuda_fp16.h>
#include <stdint.h>

#define NB 4
#define CH 128
#define HW 4096
#define BT 128
#define BS 64
#define THREADS 256
#define QK_PITCH 136   // 128 + 8 halfs: pitch = 68 words == 4 mod 32 -> conflict-free frag reads
#define V_PITCH 72     // 64 + 8 halfs: pitch = 36 words == 4 mod 32

__device__ __forceinline__ void mma16816(float c[4], const uint32_t a[4],
                                         uint32_t b0, uint32_t b1) {
    asm volatile(
        "mma.sync.aligned.m16n8k16.row.col.f32.f16.f16.f32 "
        "{%0,%1,%2,%3}, {%4,%5,%6,%7}, {%8,%9}, {%0,%1,%2,%3};\n"
        : "+f"(c[0]), "+f"(c[1]), "+f"(c[2]), "+f"(c[3])
        : "r"(a[0]), "r"(a[1]), "r"(a[2]), "r"(a[3]), "r"(b0), "r"(b1));
}

__device__ __forceinline__ float ex2(float x) {
    float y;
    asm("ex2.approx.ftz.f32 %0, %1;" : "=f"(y) : "f"(x));
    return y;
}

__device__ __forceinline__ uint32_t packh2(float a, float b) {
    __half2 h = __floats2half2_rn(a, b);
    return *reinterpret_cast<uint32_t*>(&h);
}

__global__ void __launch_bounds__(THREADS, 1)
attn_kernel(const float* __restrict__ Kg, const float* __restrict__ Qg,
            const float* __restrict__ Vg, float* __restrict__ Og) {
    extern __shared__ __half smem[];
    __half* Qs = smem;                   // [BT][QK_PITCH]  (t, c)
    __half* Ks = Qs + BT * QK_PITCH;     // [BS][QK_PITCH]  (s, c)
    __half* Vs = Ks + BS * QK_PITCH;     // [CH][V_PITCH]   (e, s)

    const int n  = blockIdx.y;
    const int t0 = blockIdx.x * BT;
    const size_t base = (size_t)n * CH * HW;
    const float* kb = Kg + base;
    const float* qb = Qg + base;
    const float* vb = Vg + base;
    float* ob = Og + base;

    const int tid  = threadIdx.x;
    const int warp = tid >> 5;
    const int lane = tid & 31;
    const int g    = lane >> 2;   // groupID (row within fragment)
    const int tq   = lane & 3;    // thread-in-group (col pairs)

    // ---- load Q tile transposed: q[c][t0+t] -> Qs[t][c], fp32 -> fp16
    for (int i = tid; i < CH * BT / 4; i += THREADS) {
        int c = i >> 5;
        int t = (i & 31) << 2;
        float4 f = *reinterpret_cast<const float4*>(&qb[(size_t)c * HW + t0 + t]);
        Qs[(t + 0) * QK_PITCH + c] = __float2half(f.x);
        Qs[(t + 1) * QK_PITCH + c] = __float2half(f.y);
        Qs[(t + 2) * QK_PITCH + c] = __float2half(f.z);
        Qs[(t + 3) * QK_PITCH + c] = __float2half(f.w);
    }
    __syncthreads();

    // ---- Q A-fragments resident in registers: warp owns rows warp*16 .. +15
    uint32_t qa[8][4];
    {
        int r = warp * 16 + g;
        #pragma unroll
        for (int kk = 0; kk < 8; kk++) {
            int c0 = kk * 16 + tq * 2;
            qa[kk][0] = *reinterpret_cast<const uint32_t*>(&Qs[r * QK_PITCH + c0]);
            qa[kk][1] = *reinterpret_cast<const uint32_t*>(&Qs[(r + 8) * QK_PITCH + c0]);
            qa[kk][2] = *reinterpret_cast<const uint32_t*>(&Qs[r * QK_PITCH + c0 + 8]);
            qa[kk][3] = *reinterpret_cast<const uint32_t*>(&Qs[(r + 8) * QK_PITCH + c0 + 8]);
        }
    }

    // log2(e) / sqrt(128): folds both the 1/sqrt(c) scale and base-2 exp
    const float kf = 0.12751742562077963f;

    float mrow0 = -1e30f, mrow1 = -1e30f;   // running max, rows g and g+8
    float lrow0 = 0.f, lrow1 = 0.f;         // running sum
    float o[16][4];
    #pragma unroll
    for (int j = 0; j < 16; j++)
        o[j][0] = o[j][1] = o[j][2] = o[j][3] = 0.f;

    for (int s0 = 0; s0 < HW; s0 += BS) {
        __syncthreads();   // previous tile's smem reads done before overwrite
        // K tile: k[c][s0+s] -> Ks[s][c] (transpose)
        for (int i = tid; i < CH * BS / 4; i += THREADS) {
            int c = i >> 4;
            int s = (i & 15) << 2;
            float4 f = *reinterpret_cast<const float4*>(&kb[(size_t)c * HW + s0 + s]);
            Ks[(s + 0) * QK_PITCH + c] = __float2half(f.x);
            Ks[(s + 1) * QK_PITCH + c] = __float2half(f.y);
            Ks[(s + 2) * QK_PITCH + c] = __float2half(f.z);
            Ks[(s + 3) * QK_PITCH + c] = __float2half(f.w);
        }
        // V tile: v[e][s0+s] -> Vs[e][s] (layout preserved; B col-major for PV)
        for (int i = tid; i < CH * BS / 4; i += THREADS) {
            int e = i >> 4;
            int s = (i & 15) << 2;
            float4 f = *reinterpret_cast<const float4*>(&vb[(size_t)e * HW + s0 + s]);
            __half2* dst = reinterpret_cast<__half2*>(&Vs[e * V_PITCH + s]);
            dst[0] = __floats2half2_rn(f.x, f.y);
            dst[1] = __floats2half2_rn(f.z, f.w);
        }
        __syncthreads();

        // ---- S = Q·K^T for this warp's 16 rows x 64 cols
        float sacc[8][4];
        #pragma unroll
        for (int j = 0; j < 8; j++)
            sacc[j][0] = sacc[j][1] = sacc[j][2] = sacc[j][3] = 0.f;

        #pragma unroll
        for (int kk = 0; kk < 8; kk++) {
            #pragma unroll
            for (int j = 0; j < 8; j++) {
                const __half* brow = &Ks[(8 * j + g) * QK_PITCH + 16 * kk + 2 * tq];
                uint32_t b0 = *reinterpret_cast<const uint32_t*>(brow);
                uint32_t b1 = *reinterpret_cast<const uint32_t*>(brow + 8);
                mma16816(sacc[j], qa[kk], b0, b1);
            }
        }

        // ---- online softmax (raw-dot domain; kf applies scale+log2e inside ex2)
        float mx0 = -1e30f, mx1 = -1e30f;
        #pragma unroll
        for (int j = 0; j < 8; j++) {
            mx0 = fmaxf(mx0, fmaxf(sacc[j][0], sacc[j][1]));
            mx1 = fmaxf(mx1, fmaxf(sacc[j][2], sacc[j][3]));
        }
        mx0 = fmaxf(mx0, __shfl_xor_sync(0xffffffffu, mx0, 1));
        mx0 = fmaxf(mx0, __shfl_xor_sync(0xffffffffu, mx0, 2));
        mx1 = fmaxf(mx1, __shfl_xor_sync(0xffffffffu, mx1, 1));
        mx1 = fmaxf(mx1, __shfl_xor_sync(0xffffffffu, mx1, 2));

        float mn0 = fmaxf(mrow0, mx0);
        float mn1 = fmaxf(mrow1, mx1);
        float alpha0 = ex2(kf * (mrow0 - mn0));
        float alpha1 = ex2(kf * (mrow1 - mn1));
        mrow0 = mn0; mrow1 = mn1;

        float rs0 = 0.f, rs1 = 0.f;
        #pragma unroll
        for (int j = 0; j < 8; j++) {
            sacc[j][0] = ex2(kf * (sacc[j][0] - mn0));
            sacc[j][1] = ex2(kf * (sacc[j][1] - mn0));
            sacc[j][2] = ex2(kf * (sacc[j][2] - mn1));
            sacc[j][3] = ex2(kf * (sacc[j][3] - mn1));
            rs0 += sacc[j][0] + sacc[j][1];
            rs1 += sacc[j][2] + sacc[j][3];
        }
        rs0 += __shfl_xor_sync(0xffffffffu, rs0, 1);
        rs0 += __shfl_xor_sync(0xffffffffu, rs0, 2);
        rs1 += __shfl_xor_sync(0xffffffffu, rs1, 1);
        rs1 += __shfl_xor_sync(0xffffffffu, rs1, 2);
        lrow0 = lrow0 * alpha0 + rs0;
        lrow1 = lrow1 * alpha1 + rs1;

        #pragma unroll
        for (int j = 0; j < 16; j++) {
            o[j][0] *= alpha0; o[j][1] *= alpha0;
            o[j][2] *= alpha1; o[j][3] *= alpha1;
        }

        // ---- P (C-frag layout) -> A-fragments for PV mma
        uint32_t pa[4][4];
        #pragma unroll
        for (int kk = 0; kk < 4; kk++) {
            pa[kk][0] = packh2(sacc[2 * kk][0],     sacc[2 * kk][1]);
            pa[kk][1] = packh2(sacc[2 * kk][2],     sacc[2 * kk][3]);
            pa[kk][2] = packh2(sacc[2 * kk + 1][0], sacc[2 * kk + 1][1]);
            pa[kk][3] = packh2(sacc[2 * kk + 1][2], sacc[2 * kk + 1][3]);
        }

        // ---- O += P·V   (B = V stored (e,s) row-major == (s,e) col-major)
        #pragma unroll
        for (int kk = 0; kk < 4; kk++) {
            #pragma unroll
            for (int je = 0; je < 16; je++) {
                const __half* brow = &Vs[(8 * je + g) * V_PITCH + 16 * kk + 2 * tq];
                uint32_t b0 = *reinterpret_cast<const uint32_t*>(brow);
                uint32_t b1 = *reinterpret_cast<const uint32_t*>(brow + 8);
                mma16816(o[je], pa[kk], b0, b1);
            }
        }
    }

    // ---- normalize and write transposed output out[n][e][t]
    float inv0 = 1.f / lrow0;
    float inv1 = 1.f / lrow1;
    int r = t0 + warp * 16 + g;
    #pragma unroll
    for (int je = 0; je < 16; je++) {
        int e = 8 * je + 2 * tq;
        ob[(size_t)e * HW + r]             = o[je][0] * inv0;
        ob[(size_t)(e + 1) * HW + r]       = o[je][1] * inv0;
        ob[(size_t)e * HW + r + 8]         = o[je][2] * inv1;
        ob[(size_t)(e + 1) * HW + r + 8]   = o[je][3] * inv1;
    }
}

extern "C" void kernel_launch(void* const* d_in, const int* in_sizes, int n_in,
                              void* d_out, int out_size) {
    const float* k = (const float*)d_in[0];   // key
    const float* q = (const float*)d_in[1];   // query
    const float* v = (const float*)d_in[2];   // value
    float* o = (float*)d_out;

    size_t smem_bytes = (size_t)(BT * QK_PITCH + BS * QK_PITCH + CH * V_PITCH) * sizeof(__half);
    cudaFuncSetAttribute((const void*)attn_kernel,
                         cudaFuncAttributeMaxDynamicSharedMemorySize, (int)smem_bytes);
    dim3 grid(HW / BT, NB);
    attn_kernel<<<grid, THREADS, (int)smem_bytes>>>(k, q, v, o);
}